// round 1
// baseline (speedup 1.0000x reference)
#include <cuda_runtime.h>
#include <cuda_bf16.h>

// ---------------------------------------------------------------------------
// FFAttention (PVT-style spatial-reduction attention), fp32 baseline.
// B=8, C=256, H=W=64, HEADS=8, d=32, R=4  -> N=4096 tokens, Nr=256 reduced.
// ---------------------------------------------------------------------------

#define B_     8
#define C_     256
#define HW_    4096          // 64*64
#define NR_    256           // 16*16
#define HEADS_ 8
#define DH_    32            // C/HEADS
#define EPS_   1e-6f

// Scratch (static device allocations are the sanctioned path)
__device__ float g_xr[B_ * NR_ * C_];          // [p=b*256+pix][c]   2 MB
__device__ float g_kv[B_ * NR_ * 2 * C_];      // [p][oc] oc<256:k   4 MB
__device__ float g_q [B_ * HW_ * C_];          // [b*4096+n][o]     33 MB
__device__ float g_ao[B_ * C_ * HW_];          // [b][oc][n]        33 MB

// ---------------------------------------------------------------------------
// Generic tiled SGEMM: C[m][n] = sum_k A(m,k) * B(k,n)
// AMODE: 0 = a_m contiguous (load m-fastest), 1 = a_k contiguous (k-fastest),
//        2 = implicit-im2col gather for the strided conv (k-fastest)
// BMODE: 0 = b_n contiguous (n-fastest), 1 = b_k contiguous (k-fastest)
// ---------------------------------------------------------------------------
__device__ __forceinline__ long conv_a_addr(int m, int k) {
    // m = b*256 + i*16 + j ; k = c*16 + r1*4 + r2
    int b  = m >> 8;
    int pix = m & 255;
    int i  = pix >> 4, j = pix & 15;
    int c  = k >> 4;
    int rr = k & 15;
    int r1 = rr >> 2, r2 = rr & 3;
    return (long)b * 1048576 + (long)c * 4096 + (4 * i + r1) * 64 + (4 * j + r2);
}

template<int AMODE, int BMODE, bool EPI>
__global__ void sgemm64_kernel(const float* __restrict__ A,
                               const float* __restrict__ Bm,
                               float* __restrict__ Cm,
                               int K,
                               long a_m, long a_k, long b_k, long b_n, long c_m,
                               long aB, long bB, long cB,
                               const float* __restrict__ resid,
                               const float* __restrict__ gamma_p)
{
    constexpr int BMt = 64, BNt = 64, BKt = 16;
    __shared__ float As[BKt][BMt + 4];
    __shared__ float Bs[BKt][BNt + 4];

    const int bz = blockIdx.z;
    A  += (long)bz * aB;
    Bm += (long)bz * bB;
    const long cOff = (long)bz * cB;

    const int m0 = blockIdx.x * BMt;
    const int n0 = blockIdx.y * BNt;
    const int t  = threadIdx.x;
    const int tn = t & 15;
    const int tm = t >> 4;

    float acc[4][4];
#pragma unroll
    for (int i = 0; i < 4; i++)
#pragma unroll
        for (int j = 0; j < 4; j++) acc[i][j] = 0.f;

    for (int k0 = 0; k0 < K; k0 += BKt) {
        // --- A tile ---
#pragma unroll
        for (int r = 0; r < 4; r++) {
            int idx = t + 256 * r;
            int m, k;
            if (AMODE == 0) { m = idx & 63; k = idx >> 6; }
            else            { k = idx & 15; m = idx >> 4; }
            long addr;
            if (AMODE == 2) addr = conv_a_addr(m0 + m, k0 + k);
            else            addr = (long)(m0 + m) * a_m + (long)(k0 + k) * a_k;
            As[k][m] = A[addr];
        }
        // --- B tile ---
#pragma unroll
        for (int r = 0; r < 4; r++) {
            int idx = t + 256 * r;
            int n, k;
            if (BMODE == 0) { n = idx & 63; k = idx >> 6; }
            else            { k = idx & 15; n = idx >> 4; }
            Bs[k][n] = Bm[(long)(k0 + k) * b_k + (long)(n0 + n) * b_n];
        }
        __syncthreads();
#pragma unroll
        for (int kk = 0; kk < BKt; kk++) {
            float4 av = *(const float4*)&As[kk][tm * 4];
            float4 bv = *(const float4*)&Bs[kk][tn * 4];
            float a_[4] = {av.x, av.y, av.z, av.w};
            float b_[4] = {bv.x, bv.y, bv.z, bv.w};
#pragma unroll
            for (int i = 0; i < 4; i++)
#pragma unroll
                for (int j = 0; j < 4; j++)
                    acc[i][j] = fmaf(a_[i], b_[j], acc[i][j]);
        }
        __syncthreads();
    }

    float g = 0.f;
    if (EPI) g = gamma_p[0];
#pragma unroll
    for (int i = 0; i < 4; i++) {
        long row = cOff + (long)(m0 + tm * 4 + i) * c_m + n0 + tn * 4;
        float4 v = make_float4(acc[i][0], acc[i][1], acc[i][2], acc[i][3]);
        if (EPI) {
            float4 rs = *(const float4*)&resid[row];
            v.x = rs.x + g * v.x;
            v.y = rs.y + g * v.y;
            v.z = rs.z + g * v.z;
            v.w = rs.w + g * v.w;
        }
        *(float4*)&Cm[row] = v;
    }
}

// ---------------------------------------------------------------------------
// LayerNorm over channel dim, one block (256 threads) per reduced pixel row.
// Biased variance (torch LayerNorm semantics). In-place on g_xr.
// ---------------------------------------------------------------------------
__global__ void ln_kernel(float* __restrict__ xr,
                          const float* __restrict__ gam,
                          const float* __restrict__ bet)
{
    __shared__ float r1[8], r2[8], smu[2];
    const int p = blockIdx.x, t = threadIdx.x;
    const int lane = t & 31, w = t >> 5;
    float v = xr[(long)p * 256 + t];
    float s1 = v, s2 = v * v;
#pragma unroll
    for (int off = 16; off; off >>= 1) {
        s1 += __shfl_xor_sync(0xffffffffu, s1, off);
        s2 += __shfl_xor_sync(0xffffffffu, s2, off);
    }
    if (lane == 0) { r1[w] = s1; r2[w] = s2; }
    __syncthreads();
    if (t == 0) {
        float a = 0.f, q = 0.f;
#pragma unroll
        for (int i = 0; i < 8; i++) { a += r1[i]; q += r2[i]; }
        float mu  = a * (1.f / 256.f);
        float var = q * (1.f / 256.f) - mu * mu;
        smu[0] = mu;
        smu[1] = rsqrtf(var + EPS_);
    }
    __syncthreads();
    float mu = smu[0], inv = smu[1];
    xr[(long)p * 256 + t] = (v - mu) * inv * gam[t] + bet[t];
}

// ---------------------------------------------------------------------------
// Attention: one warp per query, K/V tiles (256 x 32) staged in padded smem.
// Block = 256 threads, handles 64 queries of one (b, head).
// ---------------------------------------------------------------------------
#define ATT_SMEM_FLOATS (256*33 + 256*33 + 8*256 + 32*65)

__global__ void attn_kernel(const float* __restrict__ q,
                            const float* __restrict__ kv,
                            float* __restrict__ ao)
{
    extern __shared__ float sm[];
    float* sk = sm;                  // [256][33]
    float* sv = sk + 256 * 33;       // [256][33]
    float* sp = sv + 256 * 33;       // [8][256]
    float* so = sp + 8 * 256;        // [32][65]

    const int bh = blockIdx.y;
    const int b = bh >> 3, h = bh & 7;
    const int n0 = blockIdx.x * 64;
    const int t = threadIdx.x;
    const int lane = t & 31, warp = t >> 5;

    // stage K,V for this (b,h)
    for (int idx = t; idx < 256 * 32; idx += 256) {
        int p = idx >> 5, d = idx & 31;
        const float* base = kv + ((long)(b * 256 + p)) * 512 + h * 32 + d;
        sk[p * 33 + d] = base[0];
        sv[p * 33 + d] = base[256];
    }
    __syncthreads();

    const float scale = 0.17677669529663687f;  // 1/sqrt(32)

#pragma unroll 1
    for (int it = 0; it < 8; it++) {
        const int ln = warp * 8 + it;
        const int n  = n0 + ln;
        float qv = q[((long)(b * 4096 + n)) * 256 + h * 32 + lane];

        float s[8];
#pragma unroll
        for (int kk = 0; kk < 8; kk++) s[kk] = 0.f;
#pragma unroll
        for (int d = 0; d < 32; d++) {
            float qd = __shfl_sync(0xffffffffu, qv, d);
#pragma unroll
            for (int kk = 0; kk < 8; kk++)
                s[kk] = fmaf(qd, sk[(lane + 32 * kk) * 33 + d], s[kk]);
        }
        float mx = -1e30f;
#pragma unroll
        for (int kk = 0; kk < 8; kk++) { s[kk] *= scale; mx = fmaxf(mx, s[kk]); }
#pragma unroll
        for (int off = 16; off; off >>= 1)
            mx = fmaxf(mx, __shfl_xor_sync(0xffffffffu, mx, off));
        float sum = 0.f;
#pragma unroll
        for (int kk = 0; kk < 8; kk++) { s[kk] = __expf(s[kk] - mx); sum += s[kk]; }
#pragma unroll
        for (int off = 16; off; off >>= 1)
            sum += __shfl_xor_sync(0xffffffffu, sum, off);
        float inv = 1.f / sum;
#pragma unroll
        for (int kk = 0; kk < 8; kk++)
            sp[warp * 256 + lane + 32 * kk] = s[kk] * inv;
        __syncwarp();

        float outv = 0.f;
#pragma unroll 8
        for (int p = 0; p < 256; p++)
            outv = fmaf(sp[warp * 256 + p], sv[p * 33 + lane], outv);
        so[lane * 65 + ln] = outv;
        __syncwarp();
    }
    __syncthreads();

    // coalesced writeback: ao[b][h*32+d][n0+w]
#pragma unroll
    for (int r = 0; r < 8; r++) {
        int idx = t + 256 * r;
        int d = idx >> 6, w = idx & 63;
        ao[((long)(b * 256 + h * 32 + d)) * 4096 + n0 + w] = so[d * 65 + w];
    }
}

// ---------------------------------------------------------------------------
extern "C" void kernel_launch(void* const* d_in, const int* in_sizes, int n_in,
                              void* d_out, int out_size)
{
    const float* x      = (const float*)d_in[0];
    const float* w_q    = (const float*)d_in[1];
    const float* w_kv   = (const float*)d_in[2];
    const float* w_sr   = (const float*)d_in[3];
    const float* norm_g = (const float*)d_in[4];
    const float* norm_b = (const float*)d_in[5];
    const float* w_out  = (const float*)d_in[6];
    const float* gamma  = (const float*)d_in[7];
    float* out = (float*)d_out;

    float *xr, *kvb, *qb, *aob;
    cudaGetSymbolAddress((void**)&xr,  g_xr);
    cudaGetSymbolAddress((void**)&kvb, g_kv);
    cudaGetSymbolAddress((void**)&qb,  g_q);
    cudaGetSymbolAddress((void**)&aob, g_ao);

    // 1) strided conv as implicit-im2col GEMM: xr[p][o], M=2048,N=256,K=4096
    sgemm64_kernel<2, 1, false><<<dim3(32, 4, 1), 256>>>(
        x, w_sr, xr, 4096,
        0, 0, /*b_k=*/1, /*b_n=*/4096, /*c_m=*/256,
        0, 0, 0, nullptr, nullptr);

    // 2) LayerNorm over channels, in place
    ln_kernel<<<2048, 256>>>(xr, norm_g, norm_b);

    // 3) kv = w_kv @ xr^T : kv[p][oc], M=2048,N=512,K=256
    sgemm64_kernel<1, 1, false><<<dim3(32, 8, 1), 256>>>(
        xr, w_kv, kvb, 256,
        /*a_m=*/256, /*a_k=*/1, /*b_k=*/1, /*b_n=*/256, /*c_m=*/512,
        0, 0, 0, nullptr, nullptr);

    // 4) q = w_q @ x (token-major out): q[b*4096+n][o], per-batch M=4096,N=256,K=256
    sgemm64_kernel<0, 1, false><<<dim3(64, 4, 8), 256>>>(
        x, w_q, qb, 256,
        /*a_m=*/1, /*a_k=*/4096, /*b_k=*/1, /*b_n=*/256, /*c_m=*/256,
        /*aB=*/1048576, 0, /*cB=*/1048576, nullptr, nullptr);

    // 5) attention -> ao[b][hc][n]
    cudaFuncSetAttribute(attn_kernel, cudaFuncAttributeMaxDynamicSharedMemorySize,
                         ATT_SMEM_FLOATS * (int)sizeof(float));
    attn_kernel<<<dim3(64, 64), 256, ATT_SMEM_FLOATS * sizeof(float)>>>(qb, kvb, aob);

    // 6) out = x + gamma * (w_out @ ao) : per-batch M=256,N=4096,K=256
    sgemm64_kernel<1, 0, true><<<dim3(4, 64, 8), 256>>>(
        w_out, aob, out, 256,
        /*a_m=*/256, /*a_k=*/1, /*b_k=*/4096, /*b_n=*/1, /*c_m=*/4096,
        0, /*bB=*/1048576, /*cB=*/1048576, x, gamma);
}

// round 2
// speedup vs baseline: 1.0000x; 1.0000x over previous
#include <cuda_runtime.h>
#include <cuda_bf16.h>

// ---------------------------------------------------------------------------
// FFAttention (PVT-style spatial-reduction attention), fp32 baseline.
// B=8, C=256, H=W=64, HEADS=8, d=32, R=4  -> N=4096 tokens, Nr=256 reduced.
// ---------------------------------------------------------------------------

#define B_     8
#define C_     256
#define HW_    4096          // 64*64
#define NR_    256           // 16*16
#define HEADS_ 8
#define DH_    32            // C/HEADS
#define EPS_   1e-6f

// Scratch (static device allocations are the sanctioned path)
__device__ float g_xr[B_ * NR_ * C_];          // [p=b*256+pix][c]   2 MB
__device__ float g_kv[B_ * NR_ * 2 * C_];      // [p][oc] oc<256:k   4 MB
__device__ float g_q [B_ * HW_ * C_];          // [b*4096+n][o]     33 MB
__device__ float g_ao[B_ * C_ * HW_];          // [b][oc][n]        33 MB

// ---------------------------------------------------------------------------
// Generic tiled SGEMM: C[m][n] = sum_k A(m,k) * B(k,n)
// AMODE: 0 = a_m contiguous (load m-fastest), 1 = a_k contiguous (k-fastest),
//        2 = implicit-im2col gather for the strided conv (k-fastest)
// BMODE: 0 = b_n contiguous (n-fastest), 1 = b_k contiguous (k-fastest)
// ---------------------------------------------------------------------------
__device__ __forceinline__ long conv_a_addr(int m, int k) {
    // m = b*256 + i*16 + j ; k = c*16 + r1*4 + r2
    int b  = m >> 8;
    int pix = m & 255;
    int i  = pix >> 4, j = pix & 15;
    int c  = k >> 4;
    int rr = k & 15;
    int r1 = rr >> 2, r2 = rr & 3;
    return (long)b * 1048576 + (long)c * 4096 + (4 * i + r1) * 64 + (4 * j + r2);
}

template<int AMODE, int BMODE, bool EPI>
__global__ void sgemm64_kernel(const float* __restrict__ A,
                               const float* __restrict__ Bm,
                               float* __restrict__ Cm,
                               int K,
                               long a_m, long a_k, long b_k, long b_n, long c_m,
                               long aB, long bB, long cB,
                               const float* __restrict__ resid,
                               const float* __restrict__ gamma_p)
{
    constexpr int BMt = 64, BNt = 64, BKt = 16;
    __shared__ float As[BKt][BMt + 4];
    __shared__ float Bs[BKt][BNt + 4];

    const int bz = blockIdx.z;
    A  += (long)bz * aB;
    Bm += (long)bz * bB;
    const long cOff = (long)bz * cB;

    const int m0 = blockIdx.x * BMt;
    const int n0 = blockIdx.y * BNt;
    const int t  = threadIdx.x;
    const int tn = t & 15;
    const int tm = t >> 4;

    float acc[4][4];
#pragma unroll
    for (int i = 0; i < 4; i++)
#pragma unroll
        for (int j = 0; j < 4; j++) acc[i][j] = 0.f;

    for (int k0 = 0; k0 < K; k0 += BKt) {
        // --- A tile ---
#pragma unroll
        for (int r = 0; r < 4; r++) {
            int idx = t + 256 * r;
            int m, k;
            if (AMODE == 0) { m = idx & 63; k = idx >> 6; }
            else            { k = idx & 15; m = idx >> 4; }
            long addr;
            if (AMODE == 2) addr = conv_a_addr(m0 + m, k0 + k);
            else            addr = (long)(m0 + m) * a_m + (long)(k0 + k) * a_k;
            As[k][m] = A[addr];
        }
        // --- B tile ---
#pragma unroll
        for (int r = 0; r < 4; r++) {
            int idx = t + 256 * r;
            int n, k;
            if (BMODE == 0) { n = idx & 63; k = idx >> 6; }
            else            { k = idx & 15; n = idx >> 4; }
            Bs[k][n] = Bm[(long)(k0 + k) * b_k + (long)(n0 + n) * b_n];
        }
        __syncthreads();
#pragma unroll
        for (int kk = 0; kk < BKt; kk++) {
            float4 av = *(const float4*)&As[kk][tm * 4];
            float4 bv = *(const float4*)&Bs[kk][tn * 4];
            float a_[4] = {av.x, av.y, av.z, av.w};
            float b_[4] = {bv.x, bv.y, bv.z, bv.w};
#pragma unroll
            for (int i = 0; i < 4; i++)
#pragma unroll
                for (int j = 0; j < 4; j++)
                    acc[i][j] = fmaf(a_[i], b_[j], acc[i][j]);
        }
        __syncthreads();
    }

    float g = 0.f;
    if (EPI) g = gamma_p[0];
#pragma unroll
    for (int i = 0; i < 4; i++) {
        long row = cOff + (long)(m0 + tm * 4 + i) * c_m + n0 + tn * 4;
        float4 v = make_float4(acc[i][0], acc[i][1], acc[i][2], acc[i][3]);
        if (EPI) {
            float4 rs = *(const float4*)&resid[row];
            v.x = rs.x + g * v.x;
            v.y = rs.y + g * v.y;
            v.z = rs.z + g * v.z;
            v.w = rs.w + g * v.w;
        }
        *(float4*)&Cm[row] = v;
    }
}

// ---------------------------------------------------------------------------
// LayerNorm over channel dim, one block (256 threads) per reduced pixel row.
// Biased variance (torch LayerNorm semantics). In-place on g_xr.
// ---------------------------------------------------------------------------
__global__ void ln_kernel(float* __restrict__ xr,
                          const float* __restrict__ gam,
                          const float* __restrict__ bet)
{
    __shared__ float r1[8], r2[8], smu[2];
    const int p = blockIdx.x, t = threadIdx.x;
    const int lane = t & 31, w = t >> 5;
    float v = xr[(long)p * 256 + t];
    float s1 = v, s2 = v * v;
#pragma unroll
    for (int off = 16; off; off >>= 1) {
        s1 += __shfl_xor_sync(0xffffffffu, s1, off);
        s2 += __shfl_xor_sync(0xffffffffu, s2, off);
    }
    if (lane == 0) { r1[w] = s1; r2[w] = s2; }
    __syncthreads();
    if (t == 0) {
        float a = 0.f, q = 0.f;
#pragma unroll
        for (int i = 0; i < 8; i++) { a += r1[i]; q += r2[i]; }
        float mu  = a * (1.f / 256.f);
        float var = q * (1.f / 256.f) - mu * mu;
        smu[0] = mu;
        smu[1] = rsqrtf(var + EPS_);
    }
    __syncthreads();
    float mu = smu[0], inv = smu[1];
    xr[(long)p * 256 + t] = (v - mu) * inv * gam[t] + bet[t];
}

// ---------------------------------------------------------------------------
// Attention: one warp per query, K/V tiles (256 x 32) staged in padded smem.
// Block = 256 threads, handles 64 queries of one (b, head).
// ---------------------------------------------------------------------------
#define ATT_SMEM_FLOATS (256*33 + 256*33 + 8*256 + 32*65)

__global__ void attn_kernel(const float* __restrict__ q,
                            const float* __restrict__ kv,
                            float* __restrict__ ao)
{
    extern __shared__ float sm[];
    float* sk = sm;                  // [256][33]
    float* sv = sk + 256 * 33;       // [256][33]
    float* sp = sv + 256 * 33;       // [8][256]
    float* so = sp + 8 * 256;        // [32][65]

    const int bh = blockIdx.y;
    const int b = bh >> 3, h = bh & 7;
    const int n0 = blockIdx.x * 64;
    const int t = threadIdx.x;
    const int lane = t & 31, warp = t >> 5;

    // stage K,V for this (b,h)
    for (int idx = t; idx < 256 * 32; idx += 256) {
        int p = idx >> 5, d = idx & 31;
        const float* base = kv + ((long)(b * 256 + p)) * 512 + h * 32 + d;
        sk[p * 33 + d] = base[0];
        sv[p * 33 + d] = base[256];
    }
    __syncthreads();

    const float scale = 0.17677669529663687f;  // 1/sqrt(32)

#pragma unroll 1
    for (int it = 0; it < 8; it++) {
        const int ln = warp * 8 + it;
        const int n  = n0 + ln;
        float qv = q[((long)(b * 4096 + n)) * 256 + h * 32 + lane];

        float s[8];
#pragma unroll
        for (int kk = 0; kk < 8; kk++) s[kk] = 0.f;
#pragma unroll
        for (int d = 0; d < 32; d++) {
            float qd = __shfl_sync(0xffffffffu, qv, d);
#pragma unroll
            for (int kk = 0; kk < 8; kk++)
                s[kk] = fmaf(qd, sk[(lane + 32 * kk) * 33 + d], s[kk]);
        }
        float mx = -1e30f;
#pragma unroll
        for (int kk = 0; kk < 8; kk++) { s[kk] *= scale; mx = fmaxf(mx, s[kk]); }
#pragma unroll
        for (int off = 16; off; off >>= 1)
            mx = fmaxf(mx, __shfl_xor_sync(0xffffffffu, mx, off));
        float sum = 0.f;
#pragma unroll
        for (int kk = 0; kk < 8; kk++) { s[kk] = __expf(s[kk] - mx); sum += s[kk]; }
#pragma unroll
        for (int off = 16; off; off >>= 1)
            sum += __shfl_xor_sync(0xffffffffu, sum, off);
        float inv = 1.f / sum;
#pragma unroll
        for (int kk = 0; kk < 8; kk++)
            sp[warp * 256 + lane + 32 * kk] = s[kk] * inv;
        __syncwarp();

        float outv = 0.f;
#pragma unroll 8
        for (int p = 0; p < 256; p++)
            outv = fmaf(sp[warp * 256 + p], sv[p * 33 + lane], outv);
        so[lane * 65 + ln] = outv;
        __syncwarp();
    }
    __syncthreads();

    // coalesced writeback: ao[b][h*32+d][n0+w]
#pragma unroll
    for (int r = 0; r < 8; r++) {
        int idx = t + 256 * r;
        int d = idx >> 6, w = idx & 63;
        ao[((long)(b * 256 + h * 32 + d)) * 4096 + n0 + w] = so[d * 65 + w];
    }
}

// ---------------------------------------------------------------------------
extern "C" void kernel_launch(void* const* d_in, const int* in_sizes, int n_in,
                              void* d_out, int out_size)
{
    const float* x      = (const float*)d_in[0];
    const float* w_q    = (const float*)d_in[1];
    const float* w_kv   = (const float*)d_in[2];
    const float* w_sr   = (const float*)d_in[3];
    const float* norm_g = (const float*)d_in[4];
    const float* norm_b = (const float*)d_in[5];
    const float* w_out  = (const float*)d_in[6];
    const float* gamma  = (const float*)d_in[7];
    float* out = (float*)d_out;

    float *xr, *kvb, *qb, *aob;
    cudaGetSymbolAddress((void**)&xr,  g_xr);
    cudaGetSymbolAddress((void**)&kvb, g_kv);
    cudaGetSymbolAddress((void**)&qb,  g_q);
    cudaGetSymbolAddress((void**)&aob, g_ao);

    // 1) strided conv as implicit-im2col GEMM: xr[p][o], M=2048,N=256,K=4096
    sgemm64_kernel<2, 1, false><<<dim3(32, 4, 1), 256>>>(
        x, w_sr, xr, 4096,
        0, 0, /*b_k=*/1, /*b_n=*/4096, /*c_m=*/256,
        0, 0, 0, nullptr, nullptr);

    // 2) LayerNorm over channels, in place
    ln_kernel<<<2048, 256>>>(xr, norm_g, norm_b);

    // 3) kv = w_kv @ xr^T : kv[p][oc], M=2048,N=512,K=256
    sgemm64_kernel<1, 1, false><<<dim3(32, 8, 1), 256>>>(
        xr, w_kv, kvb, 256,
        /*a_m=*/256, /*a_k=*/1, /*b_k=*/1, /*b_n=*/256, /*c_m=*/512,
        0, 0, 0, nullptr, nullptr);

    // 4) q = w_q @ x (token-major out): q[b*4096+n][o], per-batch M=4096,N=256,K=256
    sgemm64_kernel<0, 1, false><<<dim3(64, 4, 8), 256>>>(
        x, w_q, qb, 256,
        /*a_m=*/1, /*a_k=*/4096, /*b_k=*/1, /*b_n=*/256, /*c_m=*/256,
        /*aB=*/1048576, 0, /*cB=*/1048576, nullptr, nullptr);

    // 5) attention -> ao[b][hc][n]
    cudaFuncSetAttribute(attn_kernel, cudaFuncAttributeMaxDynamicSharedMemorySize,
                         ATT_SMEM_FLOATS * (int)sizeof(float));
    attn_kernel<<<dim3(64, 64), 256, ATT_SMEM_FLOATS * sizeof(float)>>>(qb, kvb, aob);

    // 6) out = x + gamma * (w_out @ ao) : per-batch M=256,N=4096,K=256
    sgemm64_kernel<1, 0, true><<<dim3(4, 64, 8), 256>>>(
        w_out, aob, out, 256,
        /*a_m=*/256, /*a_k=*/1, /*b_k=*/4096, /*b_n=*/1, /*c_m=*/4096,
        0, /*bB=*/1048576, /*cB=*/1048576, x, gamma);
}

// round 5
// speedup vs baseline: 6.5163x; 6.5162x over previous
#include <cuda_runtime.h>
#include <cuda_bf16.h>
#include <cstdint>

#define BF __nv_bfloat16
#define SCALE_ 0.17677669529663687f

// ---------------- scratch ----------------
__device__ __align__(16) BF    g_A  [2048u*4096u];
__device__ __align__(16) BF    g_wsr[1048576];
__device__ __align__(16) BF    g_wq [65536], g_wkv[131072], g_wo[65536];
__device__ __align__(16) float g_prt[4u*2048u*256u];
__device__ __align__(16) BF    g_xr [2048u*256u];
__device__ __align__(16) BF    g_kv [2048u*512u];
__device__ __align__(16) BF    g_xT [32768u*256u];
__device__ __align__(16) BF    g_qb [32768u*256u];
__device__ __align__(16) BF    g_ao [32768u*256u];
__device__ __align__(16) BF    g_vt [64u*8192u];    // per-(b,h) V^T [32][256]

__device__ __forceinline__ uint32_t pk(float a, float b) {
    __nv_bfloat162 t; t.x = __float2bfloat16(a); t.y = __float2bfloat16(b);
    return *reinterpret_cast<uint32_t*>(&t);
}
__device__ __forceinline__ void mma16816(float* d, const uint32_t* a, const uint32_t* b) {
    asm volatile("mma.sync.aligned.m16n8k16.row.col.f32.bf16.bf16.f32 "
                 "{%0,%1,%2,%3}, {%4,%5,%6,%7}, {%8,%9}, {%0,%1,%2,%3};"
                 : "+f"(d[0]), "+f"(d[1]), "+f"(d[2]), "+f"(d[3])
                 : "r"(a[0]), "r"(a[1]), "r"(a[2]), "r"(a[3]), "r"(b[0]), "r"(b[1]));
}

// ---------------- prep kernels ----------------
__global__ void cvt_k(const float* __restrict__ s, BF* __restrict__ d, int n4) {
    int i = blockIdx.x * 256 + threadIdx.x;
    if (i >= n4) return;
    float4 v = ((const float4*)s)[i];
    ((uint2*)d)[i] = make_uint2(pk(v.x, v.y), pk(v.z, v.w));
}
__global__ void im2col_k(const float* __restrict__ x, BF* __restrict__ A) {
    int g = blockIdx.x * 256 + threadIdx.x;      // 2048*1024
    int p = g >> 10, r = g & 1023, c = r >> 2, r1 = r & 3;
    int b = p >> 8, i = (p >> 4) & 15, j = p & 15;
    float4 v = *(const float4*)(x + (long)b * 1048576 + (long)c * 4096 + (4 * i + r1) * 64 + 4 * j);
    *(uint2*)(A + (long)p * 4096 + c * 16 + r1 * 4) = make_uint2(pk(v.x, v.y), pk(v.z, v.w));
}
__global__ void xT_k(const float* __restrict__ x, BF* __restrict__ T) {
    __shared__ float sm[32][33];
    int b = blockIdx.z, c0 = blockIdx.y * 32, n0 = blockIdx.x * 32;
    int tx = threadIdx.x & 31, ty = threadIdx.x >> 5;
#pragma unroll
    for (int r = 0; r < 4; r++)
        sm[ty + 8 * r][tx] = x[(long)b * 1048576 + (long)(c0 + ty + 8 * r) * 4096 + n0 + tx];
    __syncthreads();
#pragma unroll
    for (int r = 0; r < 4; r++)
        T[((long)(b * 4096 + n0 + ty + 8 * r)) * 256 + c0 + tx] = __float2bfloat16(sm[tx][ty + 8 * r]);
}
__global__ void lnred_k(const float* __restrict__ part, const float* __restrict__ gam,
                        const float* __restrict__ bet, BF* __restrict__ o) {
    __shared__ float r1[8], r2[8], smu[2];
    int p = blockIdx.x, t = threadIdx.x, lane = t & 31, w = t >> 5;
    float v = 0.f;
#pragma unroll
    for (int z = 0; z < 4; z++) v += part[(long)z * 524288 + (long)p * 256 + t];
    float s1 = v, s2 = v * v;
#pragma unroll
    for (int off = 16; off; off >>= 1) {
        s1 += __shfl_xor_sync(0xffffffffu, s1, off);
        s2 += __shfl_xor_sync(0xffffffffu, s2, off);
    }
    if (lane == 0) { r1[w] = s1; r2[w] = s2; }
    __syncthreads();
    if (t == 0) {
        float a = 0.f, q = 0.f;
#pragma unroll
        for (int i = 0; i < 8; i++) { a += r1[i]; q += r2[i]; }
        float mu = a * (1.f / 256.f);
        smu[0] = mu; smu[1] = rsqrtf(q * (1.f / 256.f) - mu * mu + 1e-6f);
    }
    __syncthreads();
    o[(long)p * 256 + t] = __float2bfloat16((v - smu[0]) * smu[1] * gam[t] + bet[t]);
}
__global__ void vtp_k(const BF* __restrict__ kv, BF* __restrict__ vt) {
    int bh = blockIdx.x, b = bh >> 3, h = bh & 7, j = threadIdx.x;
    const BF* vp = kv + ((long)(b * 256 + j)) * 512 + 256 + h * 32;
    BF* o = vt + (long)bh * 8192 + j;
#pragma unroll
    for (int d = 0; d < 32; d++) o[d * 256] = vp[d];
}

// ---------------- bf16 MMA GEMM: D[m][n] = sum_k A[m,k]*B[n,k] ----------------
// BM=128 BN=128 BK=32, 8 warps (4m x 2n), warp 32x64
// EPI 0: f32 partial -> Cf + z*524288   EPI 1: bf16 -> Cb   EPI 2: residual transpose -> Cf
template <int EPI>
__global__ void __launch_bounds__(256) gemm_k(
    const BF* __restrict__ A, int lda, const BF* __restrict__ Bm, int ldb, int kChunks,
    float* __restrict__ Cf, BF* __restrict__ Cb, int ldc,
    const float* __restrict__ resid, const float* __restrict__ gp)
{
    __shared__ __align__(16) char smem[20480];
    BF* sA = (BF*)smem;            // [128][40]
    BF* sB = (BF*)(smem + 10240);  // [128][40]

    int tid = threadIdx.x, warp = tid >> 5, lane = tid & 31;
    int wm = warp & 3, wn = warp >> 2;
    int lq = lane >> 2, lr = lane & 3;
    long m0 = (long)blockIdx.x * 128;
    int n0 = blockIdx.y * 128;
    long kOff = (long)blockIdx.z * kChunks * 32;

    const BF* Ap = A + m0 * lda + kOff;
    const BF* Bp = Bm + (long)n0 * ldb + kOff;

    float acc[2][8][4];
#pragma unroll
    for (int i = 0; i < 2; i++)
#pragma unroll
        for (int j = 0; j < 8; j++)
#pragma unroll
            for (int q = 0; q < 4; q++) acc[i][j][q] = 0.f;

    uint2 ra[4], rb[4];
#pragma unroll
    for (int i = 0; i < 4; i++) {
        int idx = tid + 256 * i, row = idx >> 3, seg = idx & 7;
        ra[i] = *(const uint2*)(Ap + (long)row * lda + seg * 4);
        rb[i] = *(const uint2*)(Bp + (long)row * ldb + seg * 4);
    }

    for (int ch = 0; ch < kChunks; ch++) {
        if (ch > 0) __syncthreads();
#pragma unroll
        for (int i = 0; i < 4; i++) {
            int idx = tid + 256 * i, row = idx >> 3, seg = idx & 7;
            *(uint2*)(sA + row * 40 + seg * 4) = ra[i];
            *(uint2*)(sB + row * 40 + seg * 4) = rb[i];
        }
        __syncthreads();
        if (ch + 1 < kChunks) {
            long ko = (long)(ch + 1) * 32;
#pragma unroll
            for (int i = 0; i < 4; i++) {
                int idx = tid + 256 * i, row = idx >> 3, seg = idx & 7;
                ra[i] = *(const uint2*)(Ap + (long)row * lda + ko + seg * 4);
                rb[i] = *(const uint2*)(Bp + (long)row * ldb + ko + seg * 4);
            }
        }
#pragma unroll
        for (int ks = 0; ks < 2; ks++) {
            uint32_t af[2][4], bf[8][2];
#pragma unroll
            for (int tm = 0; tm < 2; tm++) {
                const BF* p = sA + (wm * 32 + tm * 16 + lq) * 40 + ks * 16 + lr * 2;
                af[tm][0] = *(const uint32_t*)p;
                af[tm][1] = *(const uint32_t*)(p + 8 * 40);
                af[tm][2] = *(const uint32_t*)(p + 8);
                af[tm][3] = *(const uint32_t*)(p + 8 * 40 + 8);
            }
#pragma unroll
            for (int nt = 0; nt < 8; nt++) {
                const BF* p = sB + (wn * 64 + nt * 8 + lq) * 40 + ks * 16 + lr * 2;
                bf[nt][0] = *(const uint32_t*)p;
                bf[nt][1] = *(const uint32_t*)(p + 8);
            }
#pragma unroll
            for (int tm = 0; tm < 2; tm++)
#pragma unroll
                for (int nt = 0; nt < 8; nt++)
                    mma16816(acc[tm][nt], af[tm], bf[nt]);
        }
    }

    if (EPI == 0) {
        float* out = Cf + (long)blockIdx.z * 524288 + m0 * 256 + n0;
#pragma unroll
        for (int tm = 0; tm < 2; tm++)
#pragma unroll
            for (int nt = 0; nt < 8; nt++) {
                int m = wm * 32 + tm * 16 + lq, n = wn * 64 + nt * 8 + lr * 2;
                *(float2*)(out + (long)m * 256 + n) = make_float2(acc[tm][nt][0], acc[tm][nt][1]);
                *(float2*)(out + (long)(m + 8) * 256 + n) = make_float2(acc[tm][nt][2], acc[tm][nt][3]);
            }
    } else if (EPI == 1) {
#pragma unroll
        for (int tm = 0; tm < 2; tm++)
#pragma unroll
            for (int nt = 0; nt < 8; nt++) {
                int m = wm * 32 + tm * 16 + lq, n = wn * 64 + nt * 8 + lr * 2;
                *(uint32_t*)(Cb + (m0 + m) * ldc + n0 + n) = pk(acc[tm][nt][0], acc[tm][nt][1]);
                *(uint32_t*)(Cb + (m0 + m + 8) * ldc + n0 + n) = pk(acc[tm][nt][2], acc[tm][nt][3]);
            }
    } else {
        float g = gp[0];
        int b = (int)(m0 >> 12), nb = (int)(m0 & 4095);
        float* st = (float*)smem;   // [32][132]
#pragma unroll 1
        for (int p = 0; p < 4; p++) {
            __syncthreads();
            if (wn == (p >> 1)) {
#pragma unroll
                for (int tm = 0; tm < 2; tm++)
#pragma unroll
                    for (int nl = 0; nl < 4; nl++) {
                        int nt = (p & 1) * 4 + nl;
                        int col = nl * 8 + lr * 2;
                        int row = wm * 32 + tm * 16 + lq;
                        st[col * 132 + row] = acc[tm][nt][0];
                        st[(col + 1) * 132 + row] = acc[tm][nt][1];
                        st[col * 132 + row + 8] = acc[tm][nt][2];
                        st[(col + 1) * 132 + row + 8] = acc[tm][nt][3];
                    }
            }
            __syncthreads();
#pragma unroll
            for (int it = 0; it < 4; it++) {
                int idx = tid + 256 * it;    // 1024 = 32 cols x 32 float4
                int o = idx >> 5, f4 = idx & 31;
                long ga = (long)b * 1048576 + (long)(n0 + p * 32 + o) * 4096 + nb + f4 * 4;
                float4 rs = *(const float4*)(resid + ga);
                float4 v = *(float4*)(st + o * 132 + f4 * 4);
                v.x = rs.x + g * v.x; v.y = rs.y + g * v.y;
                v.z = rs.z + g * v.z; v.w = rs.w + g * v.w;
                *(float4*)(Cf + ga) = v;
            }
        }
    }
}

// ---------------- fused attention: block = (b,h, 128 queries), 4 warps ----------------
__global__ void __launch_bounds__(128) attn_k(const BF* __restrict__ q, const BF* __restrict__ kv,
                                              const BF* __restrict__ vt, BF* __restrict__ ao)
{
    __shared__ __align__(16) BF sQ[128 * 40];
    __shared__ __align__(16) BF sK[256 * 40];
    __shared__ __align__(16) BF sV[32 * 264];

    int tid = threadIdx.x, warp = tid >> 5, lane = tid & 31;
    int lq = lane >> 2, lr = lane & 3;
    int bh = blockIdx.y, b = bh >> 3, h = bh & 7, n0 = blockIdx.x * 128;

    const BF* qp = q + ((long)(b * 4096 + n0)) * 256 + h * 32;
#pragma unroll
    for (int i = 0; i < 4; i++) {
        int idx = tid + 128 * i, row = idx >> 2, seg = idx & 3;       // 512 uint4 = 128x32
        *(uint4*)(sQ + row * 40 + seg * 8) = *(const uint4*)(qp + (long)row * 256 + seg * 8);
    }
    const BF* kp = kv + ((long)(b * 256)) * 512 + h * 32;
#pragma unroll
    for (int i = 0; i < 8; i++) {
        int idx = tid + 128 * i, row = idx >> 2, seg = idx & 3;       // 1024 uint4 = 256x32
        *(uint4*)(sK + row * 40 + seg * 8) = *(const uint4*)(kp + (long)row * 512 + seg * 8);
    }
    const BF* vp = vt + (long)bh * 8192;
#pragma unroll
    for (int i = 0; i < 16; i++) {
        int idx = tid + 128 * i, row = idx >> 6, seg = idx & 63;      // 2048 uint2 (32x256)
        *(uint2*)(sV + row * 264 + seg * 4) = *(const uint2*)(vp + row * 256 + seg * 4);
    }
    __syncthreads();

    float oacc[2][4][4];
#pragma unroll
    for (int i = 0; i < 2; i++)
#pragma unroll
        for (int j = 0; j < 4; j++)
#pragma unroll
            for (int qd = 0; qd < 4; qd++) oacc[i][j][qd] = 0.f;
    float su[2][2] = {{0.f, 0.f}, {0.f, 0.f}};

    uint32_t af[2][4];
#pragma unroll
    for (int tm = 0; tm < 2; tm++) {
        const BF* p = sQ + (warp * 32 + tm * 16 + lq) * 40 + lr * 2;
        af[tm][0] = *(const uint32_t*)p;
        af[tm][1] = *(const uint32_t*)(p + 8 * 40);
        af[tm][2] = *(const uint32_t*)(p + 8);
        af[tm][3] = *(const uint32_t*)(p + 8 * 40 + 8);
    }
    uint32_t af2[2][4];
#pragma unroll
    for (int tm = 0; tm < 2; tm++) {
        const BF* p = sQ + (warp * 32 + tm * 16 + lq) * 40 + 16 + lr * 2;
        af2[tm][0] = *(const uint32_t*)p;
        af2[tm][1] = *(const uint32_t*)(p + 8 * 40);
        af2[tm][2] = *(const uint32_t*)(p + 8);
        af2[tm][3] = *(const uint32_t*)(p + 8 * 40 + 8);
    }

#pragma unroll 1
    for (int c = 0; c < 4; c++) {           // 64-key chunks
        float sacc[2][8][4];
#pragma unroll
        for (int i = 0; i < 2; i++)
#pragma unroll
            for (int j = 0; j < 8; j++)
#pragma unroll
                for (int qd = 0; qd < 4; qd++) sacc[i][j][qd] = 0.f;

#pragma unroll
        for (int ks = 0; ks < 2; ks++) {
            uint32_t bf[8][2];
#pragma unroll
            for (int nt = 0; nt < 8; nt++) {
                const BF* p = sK + (c * 64 + nt * 8 + lq) * 40 + ks * 16 + lr * 2;
                bf[nt][0] = *(const uint32_t*)p;
                bf[nt][1] = *(const uint32_t*)(p + 8);
            }
#pragma unroll
            for (int tm = 0; tm < 2; tm++)
#pragma unroll
                for (int nt = 0; nt < 8; nt++)
                    mma16816(sacc[tm][nt], ks ? af2[tm] : af[tm], bf[nt]);
        }
        // exp + row sums (no max subtraction: |scaled logits| small)
#pragma unroll
        for (int tm = 0; tm < 2; tm++)
#pragma unroll
            for (int nt = 0; nt < 8; nt++) {
                float e0 = __expf(sacc[tm][nt][0] * SCALE_);
                float e1 = __expf(sacc[tm][nt][1] * SCALE_);
                float e2 = __expf(sacc[tm][nt][2] * SCALE_);
                float e3 = __expf(sacc[tm][nt][3] * SCALE_);
                sacc[tm][nt][0] = e0; sacc[tm][nt][1] = e1;
                sacc[tm][nt][2] = e2; sacc[tm][nt][3] = e3;
                su[tm][0] += e0 + e1;
                su[tm][1] += e2 + e3;
            }
        // P.V : repack C->A frags, k = keys
#pragma unroll
        for (int s = 0; s < 4; s++) {
            uint32_t pa[2][4];
#pragma unroll
            for (int tm = 0; tm < 2; tm++) {
                pa[tm][0] = pk(sacc[tm][2 * s][0], sacc[tm][2 * s][1]);
                pa[tm][1] = pk(sacc[tm][2 * s][2], sacc[tm][2 * s][3]);
                pa[tm][2] = pk(sacc[tm][2 * s + 1][0], sacc[tm][2 * s + 1][1]);
                pa[tm][3] = pk(sacc[tm][2 * s + 1][2], sacc[tm][2 * s + 1][3]);
            }
            uint32_t bv[4][2];
#pragma unroll
            for (int nd = 0; nd < 4; nd++) {
                const BF* p = sV + (nd * 8 + lq) * 264 + c * 64 + s * 16 + lr * 2;
                bv[nd][0] = *(const uint32_t*)p;
                bv[nd][1] = *(const uint32_t*)(p + 8);
            }
#pragma unroll
            for (int tm = 0; tm < 2; tm++)
#pragma unroll
                for (int nd = 0; nd < 4; nd++)
                    mma16816(oacc[tm][nd], pa[tm], bv[nd]);
        }
    }

    // reduce row sums across quad, normalize, store bf16
#pragma unroll
    for (int tm = 0; tm < 2; tm++)
#pragma unroll
        for (int hf = 0; hf < 2; hf++) {
            float s = su[tm][hf];
            s += __shfl_xor_sync(0xffffffffu, s, 1);
            s += __shfl_xor_sync(0xffffffffu, s, 2);
            su[tm][hf] = 1.f / s;
        }
    BF* op = ao + ((long)(b * 4096 + n0)) * 256 + h * 32;
#pragma unroll
    for (int tm = 0; tm < 2; tm++)
#pragma unroll
        for (int nd = 0; nd < 4; nd++) {
            int m = warp * 32 + tm * 16 + lq, n = nd * 8 + lr * 2;
            *(uint32_t*)(op + (long)m * 256 + n) =
                pk(oacc[tm][nd][0] * su[tm][0], oacc[tm][nd][1] * su[tm][0]);
            *(uint32_t*)(op + (long)(m + 8) * 256 + n) =
                pk(oacc[tm][nd][2] * su[tm][1], oacc[tm][nd][3] * su[tm][1]);
        }
}

// ---------------- launch ----------------
extern "C" void kernel_launch(void* const* d_in, const int* in_sizes, int n_in,
                              void* d_out, int out_size)
{
    const float* x    = (const float*)d_in[0];
    const float* w_q  = (const float*)d_in[1];
    const float* w_kv = (const float*)d_in[2];
    const float* w_sr = (const float*)d_in[3];
    const float* ng   = (const float*)d_in[4];
    const float* nb   = (const float*)d_in[5];
    const float* w_o  = (const float*)d_in[6];
    const float* gam  = (const float*)d_in[7];
    float* out = (float*)d_out;

    BF *A, *wsr, *wq, *wkv, *wo, *xr, *kv, *xT, *qb, *ao, *vt;
    float* prt;
    cudaGetSymbolAddress((void**)&A, g_A);     cudaGetSymbolAddress((void**)&wsr, g_wsr);
    cudaGetSymbolAddress((void**)&wq, g_wq);   cudaGetSymbolAddress((void**)&wkv, g_wkv);
    cudaGetSymbolAddress((void**)&wo, g_wo);   cudaGetSymbolAddress((void**)&prt, g_prt);
    cudaGetSymbolAddress((void**)&xr, g_xr);   cudaGetSymbolAddress((void**)&kv, g_kv);
    cudaGetSymbolAddress((void**)&xT, g_xT);   cudaGetSymbolAddress((void**)&qb, g_qb);
    cudaGetSymbolAddress((void**)&ao, g_ao);   cudaGetSymbolAddress((void**)&vt, g_vt);

    cvt_k<<<64, 256>>>(w_q, wq, 16384);
    cvt_k<<<128, 256>>>(w_kv, wkv, 32768);
    cvt_k<<<1024, 256>>>(w_sr, wsr, 262144);
    cvt_k<<<64, 256>>>(w_o, wo, 16384);
    im2col_k<<<8192, 256>>>(x, A);
    xT_k<<<dim3(128, 8, 8), 256>>>(x, xT);

    // conv (split-K=4): M=2048, N=256, K=4096 -> partials
    gemm_k<0><<<dim3(16, 2, 4), 256>>>(A, 4096, wsr, 4096, 32, prt, nullptr, 0, nullptr, nullptr);
    lnred_k<<<2048, 256>>>(prt, ng, nb, xr);
    // kv: M=2048, N=512, K=256
    gemm_k<1><<<dim3(16, 4, 1), 256>>>(xr, 256, wkv, 256, 8, nullptr, kv, 512, nullptr, nullptr);
    // q: M=32768, N=256, K=256
    gemm_k<1><<<dim3(256, 2, 1), 256>>>(xT, 256, wq, 256, 8, nullptr, qb, 256, nullptr, nullptr);
    vtp_k<<<64, 256>>>(kv, vt);
    attn_k<<<dim3(32, 64), 128>>>(qb, kv, vt, ao);
    // out: M=32768, N=256, K=256, residual transpose epilogue
    gemm_k<2><<<dim3(256, 2, 1), 256>>>(ao, 256, wo, 256, 8, out, nullptr, 0, x, gam);
}

// round 6
// speedup vs baseline: 7.0128x; 1.0762x over previous
#include <cuda_runtime.h>
#include <cuda_bf16.h>
#include <cstdint>

#define BF __nv_bfloat16
#define SCALE_ 0.17677669529663687f

// ---------------- scratch ----------------
__device__ __align__(16) BF    g_A  [2048u*4096u];
__device__ __align__(16) BF    g_wsr[1048576];
__device__ __align__(16) BF    g_wq [65536], g_wkv[131072], g_wo[65536];
__device__ __align__(16) float g_prt[4u*2048u*256u];
__device__ __align__(16) BF    g_xr [2048u*256u];
__device__ __align__(16) BF    g_kv [2048u*512u];
__device__ __align__(16) BF    g_xT [32768u*256u];
__device__ __align__(16) BF    g_qb [32768u*256u];
__device__ __align__(16) BF    g_ao [32768u*256u];
__device__ __align__(16) BF    g_vt [64u*8192u];    // per-(b,h) V^T [32][256]

__device__ __forceinline__ uint32_t pk(float a, float b) {
    __nv_bfloat162 t; t.x = __float2bfloat16(a); t.y = __float2bfloat16(b);
    return *reinterpret_cast<uint32_t*>(&t);
}
__device__ __forceinline__ void mma16816(float* d, const uint32_t* a, const uint32_t* b) {
    asm volatile("mma.sync.aligned.m16n8k16.row.col.f32.bf16.bf16.f32 "
                 "{%0,%1,%2,%3}, {%4,%5,%6,%7}, {%8,%9}, {%0,%1,%2,%3};"
                 : "+f"(d[0]), "+f"(d[1]), "+f"(d[2]), "+f"(d[3])
                 : "r"(a[0]), "r"(a[1]), "r"(a[2]), "r"(a[3]), "r"(b[0]), "r"(b[1]));
}
__device__ __forceinline__ void ldsm4(uint32_t* r, const BF* p) {
    uint32_t a = (uint32_t)__cvta_generic_to_shared(p);
    asm volatile("ldmatrix.sync.aligned.m8n8.x4.shared.b16 {%0,%1,%2,%3}, [%4];"
                 : "=r"(r[0]), "=r"(r[1]), "=r"(r[2]), "=r"(r[3]) : "r"(a));
}
// A-frag {a0,a1,a2,a3}: rows mb+(sel&1)*8+(lane&7), col kb+(sel>>1)*8
__device__ __forceinline__ void ldsmA(uint32_t* r, const BF* base, int mb, int kb, int ld, int lane) {
    int sel = lane >> 3, i = lane & 7;
    ldsm4(r, base + (mb + ((sel & 1) << 3) + i) * ld + kb + ((sel >> 1) << 3));
}
// B-frags for nt pair: {b0[nt],b1[nt],b0[nt+1],b1[nt+1]}: rows nb+(sel>>1)*8+(lane&7), col kb+(sel&1)*8
__device__ __forceinline__ void ldsmB(uint32_t* r, const BF* base, int nb, int kb, int ld, int lane) {
    int sel = lane >> 3, i = lane & 7;
    ldsm4(r, base + (nb + ((sel >> 1) << 3) + i) * ld + kb + ((sel & 1) << 3));
}

// ---------------- prep kernels ----------------
__global__ void cvtall_k(const float* __restrict__ wq, const float* __restrict__ wkv,
                         const float* __restrict__ wsr, const float* __restrict__ wo,
                         BF* __restrict__ dq, BF* __restrict__ dkv,
                         BF* __restrict__ dsr, BF* __restrict__ dwo) {
    int i = blockIdx.x * 256 + threadIdx.x;     // 327680 float4 total
    const float* s; BF* d; int o;
    if (i < 16384)       { s = wq;  d = dq;  o = i; }
    else if (i < 49152)  { s = wkv; d = dkv; o = i - 16384; }
    else if (i < 311296) { s = wsr; d = dsr; o = i - 49152; }
    else                 { s = wo;  d = dwo; o = i - 311296; }
    float4 v = ((const float4*)s)[o];
    ((uint2*)d)[o] = make_uint2(pk(v.x, v.y), pk(v.z, v.w));
}
__global__ void im2col_k(const float* __restrict__ x, BF* __restrict__ A) {
    int g = blockIdx.x * 256 + threadIdx.x;      // 2048*1024
    int p = g >> 10, r = g & 1023, c = r >> 2, r1 = r & 3;
    int b = p >> 8, i = (p >> 4) & 15, j = p & 15;
    float4 v = *(const float4*)(x + (long)b * 1048576 + (long)c * 4096 + (4 * i + r1) * 64 + 4 * j);
    *(uint2*)(A + (long)p * 4096 + c * 16 + r1 * 4) = make_uint2(pk(v.x, v.y), pk(v.z, v.w));
}
__global__ void xT_k(const float* __restrict__ x, BF* __restrict__ T) {
    __shared__ float sm[32][33];
    int b = blockIdx.z, c0 = blockIdx.y * 32, n0 = blockIdx.x * 32;
    int tx = threadIdx.x & 31, ty = threadIdx.x >> 5;
#pragma unroll
    for (int r = 0; r < 4; r++)
        sm[ty + 8 * r][tx] = x[(long)b * 1048576 + (long)(c0 + ty + 8 * r) * 4096 + n0 + tx];
    __syncthreads();
#pragma unroll
    for (int r = 0; r < 4; r++)
        T[((long)(b * 4096 + n0 + ty + 8 * r)) * 256 + c0 + tx] = __float2bfloat16(sm[tx][ty + 8 * r]);
}
__global__ void lnred_k(const float* __restrict__ part, const float* __restrict__ gam,
                        const float* __restrict__ bet, BF* __restrict__ o) {
    __shared__ float r1[8], r2[8], smu[2];
    int p = blockIdx.x, t = threadIdx.x, lane = t & 31, w = t >> 5;
    float v = 0.f;
#pragma unroll
    for (int z = 0; z < 4; z++) v += part[(long)z * 524288 + (long)p * 256 + t];
    float s1 = v, s2 = v * v;
#pragma unroll
    for (int off = 16; off; off >>= 1) {
        s1 += __shfl_xor_sync(0xffffffffu, s1, off);
        s2 += __shfl_xor_sync(0xffffffffu, s2, off);
    }
    if (lane == 0) { r1[w] = s1; r2[w] = s2; }
    __syncthreads();
    if (t == 0) {
        float a = 0.f, q = 0.f;
#pragma unroll
        for (int i = 0; i < 8; i++) { a += r1[i]; q += r2[i]; }
        float mu = a * (1.f / 256.f);
        smu[0] = mu; smu[1] = rsqrtf(q * (1.f / 256.f) - mu * mu + 1e-6f);
    }
    __syncthreads();
    o[(long)p * 256 + t] = __float2bfloat16((v - smu[0]) * smu[1] * gam[t] + bet[t]);
}
__global__ void vtp_k(const BF* __restrict__ kv, BF* __restrict__ vt) {
    int bh = blockIdx.x, b = bh >> 3, h = bh & 7, j = threadIdx.x;
    const BF* vp = kv + ((long)(b * 256 + j)) * 512 + 256 + h * 32;
    BF* o = vt + (long)bh * 8192 + j;
#pragma unroll
    for (int d = 0; d < 32; d++) o[d * 256] = vp[d];
}

// ---------------- bf16 MMA GEMM ----------------
template <int EPI>
__global__ void __launch_bounds__(256) gemm_k(
    const BF* __restrict__ A, int lda, const BF* __restrict__ Bm, int ldb, int kChunks,
    float* __restrict__ Cf, BF* __restrict__ Cb, int ldc,
    const float* __restrict__ resid, const float* __restrict__ gp)
{
    __shared__ __align__(16) char smem[20480];
    BF* sA = (BF*)smem;            // [128][40]
    BF* sB = (BF*)(smem + 10240);  // [128][40]

    int tid = threadIdx.x, warp = tid >> 5, lane = tid & 31;
    int wm = warp & 3, wn = warp >> 2;
    int lq = lane >> 2, lr = lane & 3;
    long m0 = (long)blockIdx.x * 128;
    int n0 = blockIdx.y * 128;
    long kOff = (long)blockIdx.z * kChunks * 32;

    const BF* Ap = A + m0 * lda + kOff;
    const BF* Bp = Bm + (long)n0 * ldb + kOff;

    float acc[2][8][4];
#pragma unroll
    for (int i = 0; i < 2; i++)
#pragma unroll
        for (int j = 0; j < 8; j++)
#pragma unroll
            for (int q = 0; q < 4; q++) acc[i][j][q] = 0.f;

    uint2 ra[4], rb[4];
#pragma unroll
    for (int i = 0; i < 4; i++) {
        int idx = tid + 256 * i, row = idx >> 3, seg = idx & 7;
        ra[i] = *(const uint2*)(Ap + (long)row * lda + seg * 4);
        rb[i] = *(const uint2*)(Bp + (long)row * ldb + seg * 4);
    }

    for (int ch = 0; ch < kChunks; ch++) {
        if (ch > 0) __syncthreads();
#pragma unroll
        for (int i = 0; i < 4; i++) {
            int idx = tid + 256 * i, row = idx >> 3, seg = idx & 7;
            *(uint2*)(sA + row * 40 + seg * 4) = ra[i];
            *(uint2*)(sB + row * 40 + seg * 4) = rb[i];
        }
        __syncthreads();
        if (ch + 1 < kChunks) {
            long ko = (long)(ch + 1) * 32;
#pragma unroll
            for (int i = 0; i < 4; i++) {
                int idx = tid + 256 * i, row = idx >> 3, seg = idx & 7;
                ra[i] = *(const uint2*)(Ap + (long)row * lda + ko + seg * 4);
                rb[i] = *(const uint2*)(Bp + (long)row * ldb + ko + seg * 4);
            }
        }
#pragma unroll
        for (int ks = 0; ks < 2; ks++) {
            uint32_t af[2][4], bf[8][2], bq[4];
#pragma unroll
            for (int tm = 0; tm < 2; tm++)
                ldsmA(af[tm], sA, wm * 32 + tm * 16, ks * 16, 40, lane);
#pragma unroll
            for (int np = 0; np < 4; np++) {
                ldsmB(bq, sB, wn * 64 + np * 16, ks * 16, 40, lane);
                bf[2 * np][0] = bq[0]; bf[2 * np][1] = bq[1];
                bf[2 * np + 1][0] = bq[2]; bf[2 * np + 1][1] = bq[3];
            }
#pragma unroll
            for (int tm = 0; tm < 2; tm++)
#pragma unroll
                for (int nt = 0; nt < 8; nt++)
                    mma16816(acc[tm][nt], af[tm], bf[nt]);
        }
    }

    if (EPI == 0) {
        float* out = Cf + (long)blockIdx.z * 524288 + m0 * 256 + n0;
#pragma unroll
        for (int tm = 0; tm < 2; tm++)
#pragma unroll
            for (int nt = 0; nt < 8; nt++) {
                int m = wm * 32 + tm * 16 + lq, n = wn * 64 + nt * 8 + lr * 2;
                *(float2*)(out + (long)m * 256 + n) = make_float2(acc[tm][nt][0], acc[tm][nt][1]);
                *(float2*)(out + (long)(m + 8) * 256 + n) = make_float2(acc[tm][nt][2], acc[tm][nt][3]);
            }
    } else if (EPI == 1) {
#pragma unroll
        for (int tm = 0; tm < 2; tm++)
#pragma unroll
            for (int nt = 0; nt < 8; nt++) {
                int m = wm * 32 + tm * 16 + lq, n = wn * 64 + nt * 8 + lr * 2;
                *(uint32_t*)(Cb + (m0 + m) * ldc + n0 + n) = pk(acc[tm][nt][0], acc[tm][nt][1]);
                *(uint32_t*)(Cb + (m0 + m + 8) * ldc + n0 + n) = pk(acc[tm][nt][2], acc[tm][nt][3]);
            }
    } else {
        float g = gp[0];
        int b = (int)(m0 >> 12), nb = (int)(m0 & 4095);
        float* st = (float*)smem;   // [32][132]
#pragma unroll 1
        for (int p = 0; p < 4; p++) {
            __syncthreads();
            if (wn == (p >> 1)) {
#pragma unroll
                for (int tm = 0; tm < 2; tm++)
#pragma unroll
                    for (int nl = 0; nl < 4; nl++) {
                        int nt = (p & 1) * 4 + nl;
                        int col = nl * 8 + lr * 2;
                        int row = wm * 32 + tm * 16 + lq;
                        st[col * 132 + row] = acc[tm][nt][0];
                        st[(col + 1) * 132 + row] = acc[tm][nt][1];
                        st[col * 132 + row + 8] = acc[tm][nt][2];
                        st[(col + 1) * 132 + row + 8] = acc[tm][nt][3];
                    }
            }
            __syncthreads();
#pragma unroll
            for (int it = 0; it < 4; it++) {
                int idx = tid + 256 * it;
                int o = idx >> 5, f4 = idx & 31;
                long ga = (long)b * 1048576 + (long)(n0 + p * 32 + o) * 4096 + nb + f4 * 4;
                float4 rs = *(const float4*)(resid + ga);
                float4 v = *(float4*)(st + o * 132 + f4 * 4);
                v.x = rs.x + g * v.x; v.y = rs.y + g * v.y;
                v.z = rs.z + g * v.z; v.w = rs.w + g * v.w;
                *(float4*)(Cf + ga) = v;
            }
        }
    }
}

// ---------------- fused attention ----------------
__global__ void __launch_bounds__(128) attn_k(const BF* __restrict__ q, const BF* __restrict__ kv,
                                              const BF* __restrict__ vt, BF* __restrict__ ao)
{
    __shared__ __align__(16) BF sQ[128 * 40];
    __shared__ __align__(16) BF sK[256 * 40];
    __shared__ __align__(16) BF sV[32 * 264];

    int tid = threadIdx.x, warp = tid >> 5, lane = tid & 31;
    int lq = lane >> 2, lr = lane & 3;
    int bh = blockIdx.y, b = bh >> 3, h = bh & 7, n0 = blockIdx.x * 128;

    const BF* qp = q + ((long)(b * 4096 + n0)) * 256 + h * 32;
#pragma unroll
    for (int i = 0; i < 4; i++) {
        int idx = tid + 128 * i, row = idx >> 2, seg = idx & 3;
        *(uint4*)(sQ + row * 40 + seg * 8) = *(const uint4*)(qp + (long)row * 256 + seg * 8);
    }
    const BF* kp = kv + ((long)(b * 256)) * 512 + h * 32;
#pragma unroll
    for (int i = 0; i < 8; i++) {
        int idx = tid + 128 * i, row = idx >> 2, seg = idx & 3;
        *(uint4*)(sK + row * 40 + seg * 8) = *(const uint4*)(kp + (long)row * 512 + seg * 8);
    }
    const BF* vp = vt + (long)bh * 8192;
#pragma unroll
    for (int i = 0; i < 16; i++) {
        int idx = tid + 128 * i, row = idx >> 6, seg = idx & 63;
        *(uint2*)(sV + row * 264 + seg * 4) = *(const uint2*)(vp + row * 256 + seg * 4);
    }
    __syncthreads();

    float oacc[2][4][4];
#pragma unroll
    for (int i = 0; i < 2; i++)
#pragma unroll
        for (int j = 0; j < 4; j++)
#pragma unroll
            for (int qd = 0; qd < 4; qd++) oacc[i][j][qd] = 0.f;
    float su[2][2] = {{0.f, 0.f}, {0.f, 0.f}};

    uint32_t af[2][4], af2[2][4];
#pragma unroll
    for (int tm = 0; tm < 2; tm++) {
        ldsmA(af[tm],  sQ, warp * 32 + tm * 16, 0,  40, lane);
        ldsmA(af2[tm], sQ, warp * 32 + tm * 16, 16, 40, lane);
    }

#pragma unroll 1
    for (int c = 0; c < 4; c++) {
        float sacc[2][8][4];
#pragma unroll
        for (int i = 0; i < 2; i++)
#pragma unroll
            for (int j = 0; j < 8; j++)
#pragma unroll
                for (int qd = 0; qd < 4; qd++) sacc[i][j][qd] = 0.f;

#pragma unroll
        for (int ks = 0; ks < 2; ks++) {
            uint32_t bf[8][2], bq[4];
#pragma unroll
            for (int np = 0; np < 4; np++) {
                ldsmB(bq, sK, c * 64 + np * 16, ks * 16, 40, lane);
                bf[2 * np][0] = bq[0]; bf[2 * np][1] = bq[1];
                bf[2 * np + 1][0] = bq[2]; bf[2 * np + 1][1] = bq[3];
            }
#pragma unroll
            for (int tm = 0; tm < 2; tm++)
#pragma unroll
                for (int nt = 0; nt < 8; nt++)
                    mma16816(sacc[tm][nt], ks ? af2[tm] : af[tm], bf[nt]);
        }
#pragma unroll
        for (int tm = 0; tm < 2; tm++)
#pragma unroll
            for (int nt = 0; nt < 8; nt++) {
                float e0 = __expf(sacc[tm][nt][0] * SCALE_);
                float e1 = __expf(sacc[tm][nt][1] * SCALE_);
                float e2 = __expf(sacc[tm][nt][2] * SCALE_);
                float e3 = __expf(sacc[tm][nt][3] * SCALE_);
                sacc[tm][nt][0] = e0; sacc[tm][nt][1] = e1;
                sacc[tm][nt][2] = e2; sacc[tm][nt][3] = e3;
                su[tm][0] += e0 + e1;
                su[tm][1] += e2 + e3;
            }
#pragma unroll
        for (int s = 0; s < 4; s++) {
            uint32_t pa[2][4];
#pragma unroll
            for (int tm = 0; tm < 2; tm++) {
                pa[tm][0] = pk(sacc[tm][2 * s][0], sacc[tm][2 * s][1]);
                pa[tm][1] = pk(sacc[tm][2 * s][2], sacc[tm][2 * s][3]);
                pa[tm][2] = pk(sacc[tm][2 * s + 1][0], sacc[tm][2 * s + 1][1]);
                pa[tm][3] = pk(sacc[tm][2 * s + 1][2], sacc[tm][2 * s + 1][3]);
            }
            uint32_t bv[4][2], bq[4];
#pragma unroll
            for (int np = 0; np < 2; np++) {
                ldsmB(bq, sV, np * 16, c * 64 + s * 16, 264, lane);
                bv[2 * np][0] = bq[0]; bv[2 * np][1] = bq[1];
                bv[2 * np + 1][0] = bq[2]; bv[2 * np + 1][1] = bq[3];
            }
#pragma unroll
            for (int tm = 0; tm < 2; tm++)
#pragma unroll
                for (int nd = 0; nd < 4; nd++)
                    mma16816(oacc[tm][nd], pa[tm], bv[nd]);
        }
    }

#pragma unroll
    for (int tm = 0; tm < 2; tm++)
#pragma unroll
        for (int hf = 0; hf < 2; hf++) {
            float s = su[tm][hf];
            s += __shfl_xor_sync(0xffffffffu, s, 1);
            s += __shfl_xor_sync(0xffffffffu, s, 2);
            su[tm][hf] = 1.f / s;
        }
    BF* op = ao + ((long)(b * 4096 + n0)) * 256 + h * 32;
#pragma unroll
    for (int tm = 0; tm < 2; tm++)
#pragma unroll
        for (int nd = 0; nd < 4; nd++) {
            int m = warp * 32 + tm * 16 + lq, n = nd * 8 + lr * 2;
            *(uint32_t*)(op + (long)m * 256 + n) =
                pk(oacc[tm][nd][0] * su[tm][0], oacc[tm][nd][1] * su[tm][0]);
            *(uint32_t*)(op + (long)(m + 8) * 256 + n) =
                pk(oacc[tm][nd][2] * su[tm][1], oacc[tm][nd][3] * su[tm][1]);
        }
}

// ---------------- launch ----------------
extern "C" void kernel_launch(void* const* d_in, const int* in_sizes, int n_in,
                              void* d_out, int out_size)
{
    const float* x    = (const float*)d_in[0];
    const float* w_q  = (const float*)d_in[1];
    const float* w_kv = (const float*)d_in[2];
    const float* w_sr = (const float*)d_in[3];
    const float* ng   = (const float*)d_in[4];
    const float* nb   = (const float*)d_in[5];
    const float* w_o  = (const float*)d_in[6];
    const float* gam  = (const float*)d_in[7];
    float* out = (float*)d_out;

    BF *A, *wsr, *wq, *wkv, *wo, *xr, *kv, *xT, *qb, *ao, *vt;
    float* prt;
    cudaGetSymbolAddress((void**)&A, g_A);     cudaGetSymbolAddress((void**)&wsr, g_wsr);
    cudaGetSymbolAddress((void**)&wq, g_wq);   cudaGetSymbolAddress((void**)&wkv, g_wkv);
    cudaGetSymbolAddress((void**)&wo, g_wo);   cudaGetSymbolAddress((void**)&prt, g_prt);
    cudaGetSymbolAddress((void**)&xr, g_xr);   cudaGetSymbolAddress((void**)&kv, g_kv);
    cudaGetSymbolAddress((void**)&xT, g_xT);   cudaGetSymbolAddress((void**)&qb, g_qb);
    cudaGetSymbolAddress((void**)&ao, g_ao);   cudaGetSymbolAddress((void**)&vt, g_vt);

    cvtall_k<<<1280, 256>>>(w_q, w_kv, w_sr, w_o, wq, wkv, wsr, wo);
    im2col_k<<<8192, 256>>>(x, A);
    xT_k<<<dim3(128, 8, 8), 256>>>(x, xT);

    gemm_k<0><<<dim3(16, 2, 4), 256>>>(A, 4096, wsr, 4096, 32, prt, nullptr, 0, nullptr, nullptr);
    lnred_k<<<2048, 256>>>(prt, ng, nb, xr);
    gemm_k<1><<<dim3(16, 4, 1), 256>>>(xr, 256, wkv, 256, 8, nullptr, kv, 512, nullptr, nullptr);
    gemm_k<1><<<dim3(256, 2, 1), 256>>>(xT, 256, wq, 256, 8, nullptr, qb, 256, nullptr, nullptr);
    vtp_k<<<64, 256>>>(kv, vt);
    attn_k<<<dim3(32, 64), 128>>>(qb, kv, vt, ao);
    gemm_k<2><<<dim3(256, 2, 1), 256>>>(ao, 256, wo, 256, 8, out, nullptr, 0, x, gam);
}